// round 14
// baseline (speedup 1.0000x reference)
#include <cuda_runtime.h>
#include <cuda_bf16.h>
#include <cuda_fp16.h>
#include <math.h>
#include <stdint.h>

// Problem constants
#define BB   128
#define SS   400
#define EE   512
#define HH   512
#define VV   50257
#define VVP  50258                // even row pitch for half2 logits
#define NOOV 50
#define VEXTN (VV + NOOV)         // 50307
#define NPB  ((VV + 127) / 128)   // 393 vocab-gemm blocks
#define NPART (NPB * 2)           // 786 partials per row

// ---------------------------------------------------------------------------
// Scratch (device globals: allocation-free per harness rules)
// ---------------------------------------------------------------------------
__device__ float g_x[BB * EE];
__device__ float g_gates[BB * 4 * HH];
__device__ float g_h1[BB * HH];
__device__ float g_c1[BB * HH];
__device__ float g_decfea[BB * HH];
__device__ float g_ctx[BB * HH];
__device__ float g_decout[BB * HH];
__device__ __align__(16) __nv_bfloat16 g_dec_bf[BB * HH];
__device__ float g_e[BB * SS];
__device__ float g_pgen[BB];
__device__ float g_pmax[NPART * BB];
__device__ float g_psum[NPART * BB];
__device__ __align__(16) __half g_logits[(size_t)BB * VVP];   // 12.9 MB fp16

__device__ __forceinline__ float sigmoidf_(float x) {
    return 1.f / (1.f + expf(-x));
}
__device__ __forceinline__ float tanh_approx(float x) {
    float y;
    asm("tanh.approx.f32 %0, %1;" : "=f"(y) : "f"(x));
    return y;
}
__device__ __forceinline__ uint32_t f2tf32(float x) {
    uint32_t o;
    asm("cvt.rna.tf32.f32 %0, %1;" : "=r"(o) : "f"(x));
    return o;
}

// ---------------------------------------------------------------------------
// Fused init: bias broadcasts for 4 GEMM outputs + zero ctx accumulator.
// ---------------------------------------------------------------------------
__global__ void fill_bias_all(float* __restrict__ px, const float* __restrict__ b_ic,
                              float* __restrict__ pgates, const float* __restrict__ b_ih,
                              float* __restrict__ pdecfea, const float* __restrict__ b_att,
                              float* __restrict__ pdecout, const float* __restrict__ b_out,
                              float* __restrict__ pctx)
{
    int i = blockIdx.x * blockDim.x + threadIdx.x;   // < 524288
    if (i < 65536) {
        px[i] = b_ic[i & 511];
    } else if (i < 327680) {
        int j = i - 65536;
        pgates[j] = b_ih[j & 2047];
    } else if (i < 393216) {
        int j = i - 327680;
        pdecfea[j] = b_att[j & 511];
    } else if (i < 458752) {
        int j = i - 393216;
        pdecout[j] = b_out[j & 511];
    } else if (i < 524288) {
        pctx[i - 458752] = 0.f;
    }
}

// ---------------------------------------------------------------------------
// Small GEMM via tf32 tensor cores, split-K with fp32 atomic reduce.
// ---------------------------------------------------------------------------
#define TP 20   // smem pitch in words

__global__ __launch_bounds__(256) void gemm_tf32_splitk(
    int N, int K, int kchunk,
    const float* __restrict__ A0, int KA0, const float* __restrict__ A1,
    const float* __restrict__ B0, int KB0, const float* __restrict__ B1,
    float* __restrict__ C)
{
    __shared__ uint32_t As[128 * TP];
    __shared__ uint32_t Bs[64 * TP];

    const int tid  = threadIdx.x;
    const int n0   = blockIdx.x * 64;
    const int kbeg = blockIdx.z * kchunk;
    const int kend = kbeg + kchunk;
    const int wid  = tid >> 5;
    const int lane = tid & 31;
    const int wm   = (wid & 3) * 32;
    const int wn   = (wid >> 2) * 32;
    const int r    = lane >> 2;
    const int c    = lane & 3;
    const int KA1  = K - KA0;
    const int KB1  = K - KB0;

    const int am0 = (tid) >> 2,        akq0 = (tid) & 3;
    const int am1 = (tid + 256) >> 2,  akq1 = (tid + 256) & 3;
    const int bn  = tid >> 2,          bkq  = tid & 3;

    float acc[2][4][4];
#pragma unroll
    for (int i = 0; i < 2; i++)
#pragma unroll
        for (int j = 0; j < 4; j++)
#pragma unroll
            for (int t = 0; t < 4; t++) acc[i][j][t] = 0.f;

    float4 aR0, aR1, bR;
    {
        int k = kbeg + akq0 * 4;
        aR0 = (k < KA0) ? *(const float4*)(A0 + (size_t)am0 * KA0 + k)
                        : *(const float4*)(A1 + (size_t)am0 * KA1 + (k - KA0));
        k = kbeg + akq1 * 4;
        aR1 = (k < KA0) ? *(const float4*)(A0 + (size_t)am1 * KA0 + k)
                        : *(const float4*)(A1 + (size_t)am1 * KA1 + (k - KA0));
        k = kbeg + bkq * 4;
        int gn = n0 + bn;
        bR = (k < KB0) ? *(const float4*)(B0 + (size_t)gn * KB0 + k)
                       : *(const float4*)(B1 + (size_t)gn * KB1 + (k - KB0));
    }

    for (int k0 = kbeg; k0 < kend; k0 += 16) {
        {
            uint4 w;
            w.x = f2tf32(aR0.x); w.y = f2tf32(aR0.y);
            w.z = f2tf32(aR0.z); w.w = f2tf32(aR0.w);
            *(uint4*)&As[am0 * TP + akq0 * 4] = w;
            w.x = f2tf32(aR1.x); w.y = f2tf32(aR1.y);
            w.z = f2tf32(aR1.z); w.w = f2tf32(aR1.w);
            *(uint4*)&As[am1 * TP + akq1 * 4] = w;
            w.x = f2tf32(bR.x); w.y = f2tf32(bR.y);
            w.z = f2tf32(bR.z); w.w = f2tf32(bR.w);
            *(uint4*)&Bs[bn * TP + bkq * 4] = w;
        }
        __syncthreads();

        if (k0 + 16 < kend) {
            int k = k0 + 16 + akq0 * 4;
            aR0 = (k < KA0) ? *(const float4*)(A0 + (size_t)am0 * KA0 + k)
                            : *(const float4*)(A1 + (size_t)am0 * KA1 + (k - KA0));
            k = k0 + 16 + akq1 * 4;
            aR1 = (k < KA0) ? *(const float4*)(A0 + (size_t)am1 * KA0 + k)
                            : *(const float4*)(A1 + (size_t)am1 * KA1 + (k - KA0));
            k = k0 + 16 + bkq * 4;
            int gn = n0 + bn;
            bR = (k < KB0) ? *(const float4*)(B0 + (size_t)gn * KB0 + k)
                           : *(const float4*)(B1 + (size_t)gn * KB1 + (k - KB0));
        }

#pragma unroll
        for (int ks = 0; ks < 2; ks++) {
            const int kk = ks * 8;
            uint32_t a[2][4];
#pragma unroll
            for (int mi = 0; mi < 2; mi++) {
                int row = wm + mi * 16 + r;
                a[mi][0] = As[row * TP + kk + c];
                a[mi][1] = As[(row + 8) * TP + kk + c];
                a[mi][2] = As[row * TP + kk + c + 4];
                a[mi][3] = As[(row + 8) * TP + kk + c + 4];
            }
            uint32_t b[4][2];
#pragma unroll
            for (int nj = 0; nj < 4; nj++) {
                int rown = wn + nj * 8 + r;
                b[nj][0] = Bs[rown * TP + kk + c];
                b[nj][1] = Bs[rown * TP + kk + c + 4];
            }
#pragma unroll
            for (int mi = 0; mi < 2; mi++)
#pragma unroll
                for (int nj = 0; nj < 4; nj++) {
                    asm volatile(
                        "mma.sync.aligned.m16n8k8.row.col.f32.tf32.tf32.f32 "
                        "{%0,%1,%2,%3}, {%4,%5,%6,%7}, {%8,%9}, {%0,%1,%2,%3};"
                        : "+f"(acc[mi][nj][0]), "+f"(acc[mi][nj][1]),
                          "+f"(acc[mi][nj][2]), "+f"(acc[mi][nj][3])
                        : "r"(a[mi][0]), "r"(a[mi][1]), "r"(a[mi][2]), "r"(a[mi][3]),
                          "r"(b[nj][0]), "r"(b[nj][1]));
                }
        }
        __syncthreads();
    }

#pragma unroll
    for (int mi = 0; mi < 2; mi++) {
        int gm = wm + mi * 16 + r;
#pragma unroll
        for (int nj = 0; nj < 4; nj++) {
            int gn = n0 + wn + nj * 8 + c * 2;
            atomicAdd(&C[(size_t)gm * N + gn],           acc[mi][nj][0]);
            atomicAdd(&C[(size_t)gm * N + gn + 1],       acc[mi][nj][1]);
            atomicAdd(&C[(size_t)(gm + 8) * N + gn],     acc[mi][nj][2]);
            atomicAdd(&C[(size_t)(gm + 8) * N + gn + 1], acc[mi][nj][3]);
        }
    }
}

// ---------------------------------------------------------------------------
// online softmax helpers
// ---------------------------------------------------------------------------
__device__ __forceinline__ void online_upd(float& m, float& s, float v) {
    if (v > m) { s = s * __expf(m - v) + 1.f; m = v; }
    else       { s += __expf(v - m); }
}
__device__ __forceinline__ void online_merge(float& m, float& s, float m2, float s2) {
    float M = fmaxf(m, m2);
    s = s * __expf(m - M) + s2 * __expf(m2 - M);
    m = M;
}

// ---------------------------------------------------------------------------
// Vocab GEMM (bf16 MMA) — BK=64 (8 iterations), register double-buffered,
// fused softmax partials, fp16 logits out.
// ---------------------------------------------------------------------------
#define VPITCH 72   // halves per smem row (144B; stride mod 128 = 16 -> conflict-free)

__global__ void vocab_gemm_mma(
    const __nv_bfloat16* __restrict__ Abf,   // [128][512]
    const float* __restrict__ B,             // [VV][512]
    const float* __restrict__ bias,
    __half* __restrict__ C,                  // [128][VVP] fp16
    float* __restrict__ pmax,
    float* __restrict__ psum)
{
    __shared__ __nv_bfloat16 As[128 * VPITCH];
    __shared__ __nv_bfloat16 Bs[128 * VPITCH];

    const int tid  = threadIdx.x;
    const int n0   = blockIdx.x * 128;
    const int wid  = tid >> 5;
    const int lane = tid & 31;
    const int warp_m = (wid & 3) * 32;
    const int warp_n = (wid >> 2) * 64;

    const uint32_t as_base = (uint32_t)__cvta_generic_to_shared(As);
    const uint32_t bs_base = (uint32_t)__cvta_generic_to_shared(Bs);

    float acc[2][8][4];
#pragma unroll
    for (int i = 0; i < 2; i++)
#pragma unroll
        for (int j = 0; j < 8; j++)
#pragma unroll
            for (int t = 0; t < 4; t++) acc[i][j][t] = 0.f;

    uint4  aR[4];    // A: 128x64 halves = 1024 x 16B / 256 thr = 4 per thread
    float4 bR[8];    // B: 128x64 fp32  = 2048 x 16B / 256 thr = 8 per thread

    auto load_regs = [&](int k0) {
#pragma unroll
        for (int r = 0; r < 4; r++) {
            int slot = tid + r * 256;
            int m = slot >> 3, kq = slot & 7;
            aR[r] = *(const uint4*)(Abf + (size_t)m * 512 + k0 + kq * 8);
        }
#pragma unroll
        for (int r = 0; r < 8; r++) {
            int slot = tid + r * 256;
            int n = slot >> 4, c4 = slot & 15;
            int gn = n0 + n;
            bR[r] = make_float4(0.f, 0.f, 0.f, 0.f);
            if (gn < VV)
                bR[r] = *(const float4*)(B + (size_t)gn * 512 + k0 + c4 * 4);
        }
    };
    auto sts = [&]() {
#pragma unroll
        for (int r = 0; r < 4; r++) {
            int slot = tid + r * 256;
            int m = slot >> 3, kq = slot & 7;
            *(uint4*)(As + m * VPITCH + kq * 8) = aR[r];
        }
#pragma unroll
        for (int r = 0; r < 8; r++) {
            int slot = tid + r * 256;
            int n = slot >> 4, c4 = slot & 15;
            __nv_bfloat162* dst = (__nv_bfloat162*)(Bs + n * VPITCH + c4 * 4);
            dst[0] = __floats2bfloat162_rn(bR[r].x, bR[r].y);
            dst[1] = __floats2bfloat162_rn(bR[r].z, bR[r].w);
        }
    };

    load_regs(0);

    for (int k0 = 0; k0 < 512; k0 += 64) {
        sts();
        __syncthreads();

        if (k0 + 64 < 512) load_regs(k0 + 64);   // overlaps MMA below

#pragma unroll
        for (int kk = 0; kk < 4; kk++) {
            const int kb = kk * 16;
            uint32_t a[2][4];
#pragma unroll
            for (int mi = 0; mi < 2; mi++) {
                int row = warp_m + mi * 16 + (lane & 15);
                int col = kb + (lane >> 4) * 8;
                uint32_t addr = as_base + (row * VPITCH + col) * 2;
                asm volatile(
                    "ldmatrix.sync.aligned.m8n8.x4.shared.b16 {%0,%1,%2,%3}, [%4];"
                    : "=r"(a[mi][0]), "=r"(a[mi][1]), "=r"(a[mi][2]), "=r"(a[mi][3])
                    : "r"(addr));
            }
            uint32_t b[8][2];
#pragma unroll
            for (int nq = 0; nq < 4; nq++) {
                int g = lane >> 3;
                int within = lane & 7;
                int row_n = warp_n + nq * 16 + within + (g >> 1) * 8;
                int colk = kb + (g & 1) * 8;
                uint32_t addr = bs_base + (row_n * VPITCH + colk) * 2;
                uint32_t r0, r1, r2, r3;
                asm volatile(
                    "ldmatrix.sync.aligned.m8n8.x4.shared.b16 {%0,%1,%2,%3}, [%4];"
                    : "=r"(r0), "=r"(r1), "=r"(r2), "=r"(r3)
                    : "r"(addr));
                b[nq * 2 + 0][0] = r0; b[nq * 2 + 0][1] = r1;
                b[nq * 2 + 1][0] = r2; b[nq * 2 + 1][1] = r3;
            }
#pragma unroll
            for (int mi = 0; mi < 2; mi++)
#pragma unroll
                for (int nj = 0; nj < 8; nj++) {
                    asm volatile(
                        "mma.sync.aligned.m16n8k16.row.col.f32.bf16.bf16.f32 "
                        "{%0,%1,%2,%3}, {%4,%5,%6,%7}, {%8,%9}, {%0,%1,%2,%3};"
                        : "+f"(acc[mi][nj][0]), "+f"(acc[mi][nj][1]),
                          "+f"(acc[mi][nj][2]), "+f"(acc[mi][nj][3])
                        : "r"(a[mi][0]), "r"(a[mi][1]), "r"(a[mi][2]), "r"(a[mi][3]),
                          "r"(b[nj][0]), "r"(b[nj][1]));
                }
        }
        __syncthreads();
    }

    // epilogue: bias + half2 store + per-row online stats
    const int pblock = blockIdx.x * 2 + (warp_n ? 1 : 0);
#pragma unroll
    for (int mi = 0; mi < 2; mi++) {
        int m = warp_m + mi * 16 + (lane >> 2);
        float m0v = -3.0e38f, s0 = 0.f;
        float m1v = -3.0e38f, s1 = 0.f;
#pragma unroll
        for (int nj = 0; nj < 8; nj++) {
            int n = n0 + warp_n + nj * 8 + (lane & 3) * 2;   // even
            if (n + 1 < VV) {
                float v0 = acc[mi][nj][0] + bias[n];
                float v1 = acc[mi][nj][1] + bias[n + 1];
                *(__half2*)(C + (size_t)m * VVP + n) = __floats2half2_rn(v0, v1);
                online_upd(m0v, s0, v0); online_upd(m0v, s0, v1);
                float w0 = acc[mi][nj][2] + bias[n];
                float w1 = acc[mi][nj][3] + bias[n + 1];
                *(__half2*)(C + (size_t)(m + 8) * VVP + n) = __floats2half2_rn(w0, w1);
                online_upd(m1v, s1, w0); online_upd(m1v, s1, w1);
            } else if (n < VV) {
                float v0 = acc[mi][nj][0] + bias[n];
                C[(size_t)m * VVP + n] = __float2half_rn(v0);
                online_upd(m0v, s0, v0);
                float w0 = acc[mi][nj][2] + bias[n];
                C[(size_t)(m + 8) * VVP + n] = __float2half_rn(w0);
                online_upd(m1v, s1, w0);
            }
        }
#pragma unroll
        for (int off = 1; off <= 2; off <<= 1) {
            float om = __shfl_xor_sync(0xffffffffu, m0v, off);
            float os = __shfl_xor_sync(0xffffffffu, s0, off);
            online_merge(m0v, s0, om, os);
            om = __shfl_xor_sync(0xffffffffu, m1v, off);
            os = __shfl_xor_sync(0xffffffffu, s1, off);
            online_merge(m1v, s1, om, os);
        }
        if ((lane & 3) == 0) {
            pmax[(size_t)pblock * BB + m]     = m0v;
            psum[(size_t)pblock * BB + m]     = s0;
            pmax[(size_t)pblock * BB + m + 8] = m1v;
            psum[(size_t)pblock * BB + m + 8] = s1;
        }
    }
}

// ---------------------------------------------------------------------------
// Fused: per-row stats reduce + final vocab distribution + copy scatter.
// ---------------------------------------------------------------------------
#define FCHUNK 6290   // even; 8*6290 >= VEXTN

__global__ __launch_bounds__(256) void final_fused_kernel(
    const __half* __restrict__ logits,
    const float* __restrict__ pmax,
    const float* __restrict__ psum,
    const float* __restrict__ pgen,
    const int*   __restrict__ ids,    // [BB][SS]
    const float* __restrict__ attn,   // [BB][SS]
    float* __restrict__ outf)
{
    const int b = blockIdx.y;
    const int tid = threadIdx.x;

    float m = -3.0e38f, s = 0.f;
    for (int i = tid; i < NPART; i += 256)
        online_merge(m, s, pmax[(size_t)i * BB + b], psum[(size_t)i * BB + b]);
    __shared__ float sm[256], ss[256];
    sm[tid] = m; ss[tid] = s; __syncthreads();
    for (int off = 128; off; off >>= 1) {
        if (tid < off) {
            float M = fmaxf(sm[tid], sm[tid + off]);
            ss[tid] = ss[tid] * __expf(sm[tid] - M) + ss[tid + off] * __expf(sm[tid + off] - M);
            sm[tid] = M;
        }
        __syncthreads();
    }
    m = sm[0]; s = ss[0];
    const float pg = pgen[b];
    const float scale = pg / s;

    const int start = blockIdx.x * FCHUNK;
    const int end = (start + FCHUNK < VEXTN) ? (start + FCHUNK) : VEXTN;
    const __half* lrow = logits + (size_t)b * VVP;
    float* orow = outf + (size_t)b * VEXTN;

    for (int n = start + tid * 2; n < end; n += 512) {
        float v0 = 0.f, v1 = 0.f;
        if (n + 1 < VV) {
            __half2 h = *(const __half2*)(lrow + n);
            float2 f = __half22float2(h);
            v0 = scale * __expf(f.x - m);
            v1 = scale * __expf(f.y - m);
        } else if (n < VV) {
            v0 = scale * __expf(__half2float(lrow[n]) - m);
        }
        orow[n] = v0;
        if (n + 1 < end) orow[n + 1] = v1;
    }

    __syncthreads();   // chunk stores complete (block-scope ordering)
    const float one_m_pg = 1.f - pg;
    for (int sidx = tid; sidx < SS; sidx += 256) {
        int id = ids[b * SS + sidx];
        if (id >= start && id < end) {
            atomicAdd(&orow[id], one_m_pg * attn[b * SS + sidx]);
        }
    }
}

// ---------------------------------------------------------------------------
// LSTM elementwise (float4 vectorized)
// ---------------------------------------------------------------------------
__global__ void lstm_elem(const float* __restrict__ gates,
                          const float* __restrict__ b_hh,
                          const float* __restrict__ c0,
                          float* __restrict__ h1, float* __restrict__ c1,
                          float* __restrict__ out_h1, float* __restrict__ out_c1)
{
    int idx = blockIdx.x * blockDim.x + threadIdx.x;
    if (idx >= BB * HH / 4) return;
    int b  = idx / (HH / 4);
    int j  = (idx % (HH / 4)) * 4;
    const float* g = gates + (size_t)b * 4 * HH;
    float4 gi = *(const float4*)(g + j);
    float4 gf = *(const float4*)(g + HH + j);
    float4 gg = *(const float4*)(g + 2 * HH + j);
    float4 go = *(const float4*)(g + 3 * HH + j);
    float4 bi = *(const float4*)(b_hh + j);
    float4 bf = *(const float4*)(b_hh + HH + j);
    float4 bg = *(const float4*)(b_hh + 2 * HH + j);
    float4 bo = *(const float4*)(b_hh + 3 * HH + j);
    float4 cprev = *(const float4*)(c0 + b * HH + j);

    float4 cc, hh;
    {
        float iv = sigmoidf_(gi.x + bi.x), fv = sigmoidf_(gf.x + bf.x);
        float gv = tanhf(gg.x + bg.x),     ov = sigmoidf_(go.x + bo.x);
        cc.x = fv * cprev.x + iv * gv; hh.x = ov * tanhf(cc.x);
        iv = sigmoidf_(gi.y + bi.y); fv = sigmoidf_(gf.y + bf.y);
        gv = tanhf(gg.y + bg.y);     ov = sigmoidf_(go.y + bo.y);
        cc.y = fv * cprev.y + iv * gv; hh.y = ov * tanhf(cc.y);
        iv = sigmoidf_(gi.z + bi.z); fv = sigmoidf_(gf.z + bf.z);
        gv = tanhf(gg.z + bg.z);     ov = sigmoidf_(go.z + bo.z);
        cc.z = fv * cprev.z + iv * gv; hh.z = ov * tanhf(cc.z);
        iv = sigmoidf_(gi.w + bi.w); fv = sigmoidf_(gf.w + bf.w);
        gv = tanhf(gg.w + bg.w);     ov = sigmoidf_(go.w + bo.w);
        cc.w = fv * cprev.w + iv * gv; hh.w = ov * tanhf(cc.w);
    }
    *(float4*)(h1 + b * HH + j) = hh;
    *(float4*)(c1 + b * HH + j) = cc;
    *(float4*)(out_h1 + b * HH + j) = hh;
    *(float4*)(out_c1 + b * HH + j) = cc;
}

// ---------------------------------------------------------------------------
// Attention energies (warp per (b,s) row), tanh.approx
// ---------------------------------------------------------------------------
__global__ void attn_e_kernel(const float* __restrict__ sf,
                              const float* __restrict__ dec_fea,
                              const float* __restrict__ cov,
                              const float* __restrict__ mask,
                              const float* __restrict__ v_att,
                              const float* __restrict__ w_c,
                              float* __restrict__ e)
{
    int gwarp = (blockIdx.x * blockDim.x + threadIdx.x) >> 5;
    int lane = threadIdx.x & 31;
    if (gwarp >= BB * SS) return;
    int b = gwarp / SS;
    float cadd = w_c[0] * cov[gwarp];

    const float4* row = (const float4*)(sf + (size_t)gwarp * HH);
    const float4* df  = (const float4*)(dec_fea + (size_t)b * HH);
    const float4* va  = (const float4*)(v_att);

    float acc = 0.f;
#pragma unroll
    for (int i = 0; i < HH / 128; i++) {
        float4 x = row[i * 32 + lane];
        float4 d = df[i * 32 + lane];
        float4 v = va[i * 32 + lane];
        acc += tanh_approx(x.x + d.x + cadd) * v.x;
        acc += tanh_approx(x.y + d.y + cadd) * v.y;
        acc += tanh_approx(x.z + d.z + cadd) * v.z;
        acc += tanh_approx(x.w + d.w + cadd) * v.w;
    }
#pragma unroll
    for (int off = 16; off; off >>= 1) acc += __shfl_xor_sync(0xffffffffu, acc, off);
    if (lane == 0) e[gwarp] = (mask[gwarp] > 0.f) ? acc : -1.0e9f;
}

// ---------------------------------------------------------------------------
// Softmax over S + mask renorm + coverage update
// ---------------------------------------------------------------------------
__global__ void softmax_s_kernel(const float* __restrict__ e,
                                 const float* __restrict__ mask,
                                 const float* __restrict__ cov,
                                 float* __restrict__ out_attn,
                                 float* __restrict__ out_cov)
{
    int b = blockIdx.x;
    int tid = threadIdx.x;           // 512 threads
    __shared__ float sh[SS];
    __shared__ float r1[512];
    __shared__ float r2[512];

    float m = -3.0e38f;
    for (int s = tid; s < SS; s += 512) m = fmaxf(m, e[b * SS + s]);
    r1[tid] = m; __syncthreads();
    for (int off = 256; off; off >>= 1) {
        if (tid < off) r1[tid] = fmaxf(r1[tid], r1[tid + off]);
        __syncthreads();
    }
    m = r1[0];
    __syncthreads();

    float P = 0.f, Q = 0.f;
    for (int s = tid; s < SS; s += 512) {
        float p = __expf(e[b * SS + s] - m);
        sh[s] = p;
        P += p;
        Q += p * mask[b * SS + s];
    }
    r1[tid] = P; r2[tid] = Q; __syncthreads();
    for (int off = 256; off; off >>= 1) {
        if (tid < off) { r1[tid] += r1[tid + off]; r2[tid] += r2[tid + off]; }
        __syncthreads();
    }
    P = r1[0]; Q = r2[0];
    float denom = Q / P + 1e-12f;

    for (int s = tid; s < SS; s += 512) {
        float a = sh[s] * mask[b * SS + s] / P / denom;
        out_attn[b * SS + s] = a;
        out_cov[b * SS + s] = cov[b * SS + s] + a;
    }
}

// ---------------------------------------------------------------------------
// Context: float4 over h; grid (B, 1, CSPLIT), 128 threads.
// ---------------------------------------------------------------------------
#define CSPLIT 4
#define CCHUNK (SS / CSPLIT)   // 100

__global__ __launch_bounds__(128) void ctx_kernel(
    const float* __restrict__ attn,
    const float* __restrict__ states,
    float* __restrict__ ctx)
{
    int b = blockIdx.x;
    int s0 = blockIdx.z * CCHUNK;
    __shared__ float sa[CCHUNK];
    if (threadIdx.x < CCHUNK) sa[threadIdx.x] = attn[b * SS + s0 + threadIdx.x];
    __syncthreads();

    const float4* st = (const float4*)(states + (size_t)b * SS * HH + (size_t)s0 * HH)
                       + threadIdx.x;
    float4 a0 = make_float4(0.f, 0.f, 0.f, 0.f);
    float4 a1 = make_float4(0.f, 0.f, 0.f, 0.f);
    float4 a2 = make_float4(0.f, 0.f, 0.f, 0.f);
    float4 a3 = make_float4(0.f, 0.f, 0.f, 0.f);
#pragma unroll 5
    for (int s = 0; s < CCHUNK; s += 4) {
        float4 v0 = st[(size_t)(s)     * (HH / 4)];
        float4 v1 = st[(size_t)(s + 1) * (HH / 4)];
        float4 v2 = st[(size_t)(s + 2) * (HH / 4)];
        float4 v3 = st[(size_t)(s + 3) * (HH / 4)];
        float c0 = sa[s], c1 = sa[s + 1], c2 = sa[s + 2], c3 = sa[s + 3];
        a0.x += c0 * v0.x; a0.y += c0 * v0.y; a0.z += c0 * v0.z; a0.w += c0 * v0.w;
        a1.x += c1 * v1.x; a1.y += c1 * v1.y; a1.z += c1 * v1.z; a1.w += c1 * v1.w;
        a2.x += c2 * v2.x; a2.y += c2 * v2.y; a2.z += c2 * v2.z; a2.w += c2 * v2.w;
        a3.x += c3 * v3.x; a3.y += c3 * v3.y; a3.z += c3 * v3.z; a3.w += c3 * v3.w;
    }
    float rx = (a0.x + a1.x) + (a2.x + a3.x);
    float ry = (a0.y + a1.y) + (a2.y + a3.y);
    float rz = (a0.z + a1.z) + (a2.z + a3.z);
    float rw = (a0.w + a1.w) + (a2.w + a3.w);
    float* dst = ctx + b * HH + threadIdx.x * 4;
    atomicAdd(dst + 0, rx);
    atomicAdd(dst + 1, ry);
    atomicAdd(dst + 2, rz);
    atomicAdd(dst + 3, rw);
}

// ---------------------------------------------------------------------------
// p_gen = sigmoid(dec_out . W_pg + b_pg); copy dec_out to output; bf16 convert
// ---------------------------------------------------------------------------
__global__ void pgen_kernel(const float* __restrict__ dec_out,
                            const float* __restrict__ W_pg,
                            const float* __restrict__ b_pg,
                            float* __restrict__ pgen,
                            float* __restrict__ out_pgen,
                            float* __restrict__ out_dec,
                            __nv_bfloat16* __restrict__ dec_bf)
{
    int b = blockIdx.x;
    int tid = threadIdx.x;            // 128 threads
    float acc = 0.f;
    for (int j = tid; j < HH; j += 128) {
        float d = dec_out[b * HH + j];
        out_dec[b * HH + j] = d;
        dec_bf[b * HH + j] = __float2bfloat16_rn(d);
        acc += d * W_pg[j];
    }
    __shared__ float red[4];
#pragma unroll
    for (int off = 16; off; off >>= 1) acc += __shfl_xor_sync(0xffffffffu, acc, off);
    if ((tid & 31) == 0) red[tid >> 5] = acc;
    __syncthreads();
    if (tid == 0) {
        float t = red[0] + red[1] + red[2] + red[3];
        float p = sigmoidf_(t + b_pg[0]);
        pgen[b] = p;
        out_pgen[b] = p;
    }
}

// ---------------------------------------------------------------------------
// Launcher
// ---------------------------------------------------------------------------
extern "C" void kernel_launch(void* const* d_in, const int* in_sizes, int n_in,
                              void* d_out, int out_size)
{
    const float* emb    = (const float*)d_in[0];
    const float* feed   = (const float*)d_in[1];
    const float* hidden = (const float*)d_in[2];
    const float* ctx0   = (const float*)d_in[3];
    const float* states = (const float*)d_in[4];
    const float* sfeat  = (const float*)d_in[5];
    const float* mask   = (const float*)d_in[6];
    const float* cov    = (const float*)d_in[7];
    const int*   srcids = (const int*)d_in[8];
    const float* W_ic   = (const float*)d_in[9];
    const float* b_ic   = (const float*)d_in[10];
    const float* W_ih   = (const float*)d_in[11];
    const float* W_hh   = (const float*)d_in[12];
    const float* b_ih   = (const float*)d_in[13];
    const float* b_hh   = (const float*)d_in[14];
    const float* W_dec  = (const float*)d_in[15];
    const float* b_att  = (const float*)d_in[16];
    const float* v_att  = (const float*)d_in[17];
    const float* w_c    = (const float*)d_in[18];
    const float* W_out  = (const float*)d_in[19];
    const float* b_out  = (const float*)d_in[20];
    const float* W_pg   = (const float*)d_in[21];
    const float* b_pg   = (const float*)d_in[22];
    const float* W_v    = (const float*)d_in[23];
    const float* b_v    = (const float*)d_in[24];

    float* out = (float*)d_out;
    float* out_final = out;
    float* out_pgen  = out_final + (size_t)BB * VEXTN;
    float* out_attn  = out_pgen + BB;
    float* out_cov   = out_attn + (size_t)BB * SS;
    float* out_h1    = out_cov + (size_t)BB * SS;
    float* out_c1    = out_h1 + (size_t)BB * HH;
    float* out_dec   = out_c1 + (size_t)BB * HH;

    float *px, *pgates, *ph1, *pc1, *pdecfea, *pctx, *pdecout;
    float *pe, *ppgen, *ppmax, *ppsum;
    __half* plogits;
    __nv_bfloat16* pdecbf;
    cudaGetSymbolAddress((void**)&px,      g_x);
    cudaGetSymbolAddress((void**)&pgates,  g_gates);
    cudaGetSymbolAddress((void**)&ph1,     g_h1);
    cudaGetSymbolAddress((void**)&pc1,     g_c1);
    cudaGetSymbolAddress((void**)&pdecfea, g_decfea);
    cudaGetSymbolAddress((void**)&pctx,    g_ctx);
    cudaGetSymbolAddress((void**)&pdecout, g_decout);
    cudaGetSymbolAddress((void**)&pdecbf,  g_dec_bf);
    cudaGetSymbolAddress((void**)&pe,      g_e);
    cudaGetSymbolAddress((void**)&ppgen,   g_pgen);
    cudaGetSymbolAddress((void**)&ppmax,   g_pmax);
    cudaGetSymbolAddress((void**)&ppsum,   g_psum);
    cudaGetSymbolAddress((void**)&plogits, g_logits);

    // 0) fused init (bias fills + ctx zero)
    fill_bias_all<<<524288 / 256, 256>>>(px, b_ic, pgates, b_ih,
                                         pdecfea, b_att, pdecout, b_out, pctx);

    // 1) x = [emb|feed] @ W_ic^T   (tf32, split 8)
    gemm_tf32_splitk<<<dim3(EE / 64, 1, 8), 256>>>(
        EE, 1024, 128, emb, EE, feed, W_ic, 1024, nullptr, px);

    // 2) gates = [x|h0] @ [W_ih|W_hh]^T   (tf32, split 8)
    gemm_tf32_splitk<<<dim3(4 * HH / 64, 1, 8), 256>>>(
        4 * HH, 1024, 128, px, EE, hidden, W_ih, EE, W_hh, pgates);

    // 3) LSTM elementwise
    lstm_elem<<<(BB * HH / 4 + 255) / 256, 256>>>(pgates, b_hh, ctx0, ph1, pc1,
                                                  out_h1, out_c1);

    // 4) dec_fea = h1 @ W_dec^T   (tf32, split 8)
    gemm_tf32_splitk<<<dim3(HH / 64, 1, 8), 256>>>(
        HH, 512, 64, ph1, 512, nullptr, W_dec, 512, nullptr, pdecfea);

    // 5) attention energies
    attn_e_kernel<<<(BB * SS) / 8, 256>>>(sfeat, pdecfea, cov, mask, v_att, w_c, pe);

    // 6) softmax over S + coverage update (writes out_attn directly)
    softmax_s_kernel<<<BB, 512>>>(pe, mask, cov, out_attn, out_cov);

    // 7) context vector (float4 over h, split-S x4, atomic reduce)
    ctx_kernel<<<dim3(BB, 1, CSPLIT), 128>>>(out_attn, states, pctx);

    // 8) dec_out = [h1|ctx] @ W_out^T   (tf32, split 8)
    gemm_tf32_splitk<<<dim3(HH / 64, 1, 8), 256>>>(
        HH, 1024, 128, ph1, HH, pctx, W_out, 1024, nullptr, pdecout);

    // 9) p_gen + dec_out output copy + bf16 convert
    pgen_kernel<<<BB, 128>>>(pdecout, W_pg, b_pg, ppgen, out_pgen, out_dec, pdecbf);

    // 10) vocab logits (bf16 MMA, BK=64) + fused softmax partials
    vocab_gemm_mma<<<NPB, 256>>>(pdecbf, W_v, b_v, plogits, ppmax, ppsum);

    // 11) fused stats reduce + final vocab distribution + copy scatter
    final_fused_kernel<<<dim3(8, BB), 256>>>(plogits, ppmax, ppsum, ppgen,
                                             srcids, out_attn, out_final);
}

// round 15
// speedup vs baseline: 1.0107x; 1.0107x over previous
#include <cuda_runtime.h>
#include <cuda_bf16.h>
#include <cuda_fp16.h>
#include <math.h>
#include <stdint.h>

// Problem constants
#define BB   128
#define SS   400
#define EE   512
#define HH   512
#define VV   50257
#define VVP  50258                // even row pitch for half2 logits
#define NOOV 50
#define VEXTN (VV + NOOV)         // 50307
#define NPB  ((VV + 127) / 128)   // 393 vocab-gemm blocks
#define NPART (NPB * 2)           // 786 partials per row

// ---------------------------------------------------------------------------
// Scratch (device globals: allocation-free per harness rules)
// ---------------------------------------------------------------------------
__device__ float g_x[BB * EE];
__device__ float g_gates[BB * 4 * HH];
__device__ float g_h1[BB * HH];
__device__ float g_c1[BB * HH];
__device__ float g_decfea[BB * HH];
__device__ float g_ctx[BB * HH];
__device__ float g_decout[BB * HH];
__device__ __align__(16) __nv_bfloat16 g_dec_bf[BB * HH];
__device__ float g_e[BB * SS];
__device__ float g_pgen[BB];
__device__ float g_pmax[NPART * BB];
__device__ float g_psum[NPART * BB];
__device__ __align__(16) __half g_logits[(size_t)BB * VVP];   // 12.9 MB fp16

__device__ __forceinline__ float sigmoidf_(float x) {
    return 1.f / (1.f + expf(-x));
}
__device__ __forceinline__ float tanh_approx(float x) {
    float y;
    asm("tanh.approx.f32 %0, %1;" : "=f"(y) : "f"(x));
    return y;
}
__device__ __forceinline__ uint32_t f2tf32(float x) {
    uint32_t o;
    asm("cvt.rna.tf32.f32 %0, %1;" : "=r"(o) : "f"(x));
    return o;
}

// ---------------------------------------------------------------------------
// Fused init: bias broadcasts for 4 GEMM outputs + zero ctx accumulator.
// ---------------------------------------------------------------------------
__global__ void fill_bias_all(float* __restrict__ px, const float* __restrict__ b_ic,
                              float* __restrict__ pgates, const float* __restrict__ b_ih,
                              float* __restrict__ pdecfea, const float* __restrict__ b_att,
                              float* __restrict__ pdecout, const float* __restrict__ b_out,
                              float* __restrict__ pctx)
{
    int i = blockIdx.x * blockDim.x + threadIdx.x;   // < 524288
    if (i < 65536) {
        px[i] = b_ic[i & 511];
    } else if (i < 327680) {
        int j = i - 65536;
        pgates[j] = b_ih[j & 2047];
    } else if (i < 393216) {
        int j = i - 327680;
        pdecfea[j] = b_att[j & 511];
    } else if (i < 458752) {
        int j = i - 393216;
        pdecout[j] = b_out[j & 511];
    } else if (i < 524288) {
        pctx[i - 458752] = 0.f;
    }
}

// ---------------------------------------------------------------------------
// Small GEMM via tf32 tensor cores, split-K with fp32 atomic reduce.
// ---------------------------------------------------------------------------
#define TP 20   // smem pitch in words

__global__ __launch_bounds__(256) void gemm_tf32_splitk(
    int N, int K, int kchunk,
    const float* __restrict__ A0, int KA0, const float* __restrict__ A1,
    const float* __restrict__ B0, int KB0, const float* __restrict__ B1,
    float* __restrict__ C)
{
    __shared__ uint32_t As[128 * TP];
    __shared__ uint32_t Bs[64 * TP];

    const int tid  = threadIdx.x;
    const int n0   = blockIdx.x * 64;
    const int kbeg = blockIdx.z * kchunk;
    const int kend = kbeg + kchunk;
    const int wid  = tid >> 5;
    const int lane = tid & 31;
    const int wm   = (wid & 3) * 32;
    const int wn   = (wid >> 2) * 32;
    const int r    = lane >> 2;
    const int c    = lane & 3;
    const int KA1  = K - KA0;
    const int KB1  = K - KB0;

    const int am0 = (tid) >> 2,        akq0 = (tid) & 3;
    const int am1 = (tid + 256) >> 2,  akq1 = (tid + 256) & 3;
    const int bn  = tid >> 2,          bkq  = tid & 3;

    float acc[2][4][4];
#pragma unroll
    for (int i = 0; i < 2; i++)
#pragma unroll
        for (int j = 0; j < 4; j++)
#pragma unroll
            for (int t = 0; t < 4; t++) acc[i][j][t] = 0.f;

    float4 aR0, aR1, bR;
    {
        int k = kbeg + akq0 * 4;
        aR0 = (k < KA0) ? *(const float4*)(A0 + (size_t)am0 * KA0 + k)
                        : *(const float4*)(A1 + (size_t)am0 * KA1 + (k - KA0));
        k = kbeg + akq1 * 4;
        aR1 = (k < KA0) ? *(const float4*)(A0 + (size_t)am1 * KA0 + k)
                        : *(const float4*)(A1 + (size_t)am1 * KA1 + (k - KA0));
        k = kbeg + bkq * 4;
        int gn = n0 + bn;
        bR = (k < KB0) ? *(const float4*)(B0 + (size_t)gn * KB0 + k)
                       : *(const float4*)(B1 + (size_t)gn * KB1 + (k - KB0));
    }

    for (int k0 = kbeg; k0 < kend; k0 += 16) {
        {
            uint4 w;
            w.x = f2tf32(aR0.x); w.y = f2tf32(aR0.y);
            w.z = f2tf32(aR0.z); w.w = f2tf32(aR0.w);
            *(uint4*)&As[am0 * TP + akq0 * 4] = w;
            w.x = f2tf32(aR1.x); w.y = f2tf32(aR1.y);
            w.z = f2tf32(aR1.z); w.w = f2tf32(aR1.w);
            *(uint4*)&As[am1 * TP + akq1 * 4] = w;
            w.x = f2tf32(bR.x); w.y = f2tf32(bR.y);
            w.z = f2tf32(bR.z); w.w = f2tf32(bR.w);
            *(uint4*)&Bs[bn * TP + bkq * 4] = w;
        }
        __syncthreads();

        if (k0 + 16 < kend) {
            int k = k0 + 16 + akq0 * 4;
            aR0 = (k < KA0) ? *(const float4*)(A0 + (size_t)am0 * KA0 + k)
                            : *(const float4*)(A1 + (size_t)am0 * KA1 + (k - KA0));
            k = k0 + 16 + akq1 * 4;
            aR1 = (k < KA0) ? *(const float4*)(A0 + (size_t)am1 * KA0 + k)
                            : *(const float4*)(A1 + (size_t)am1 * KA1 + (k - KA0));
            k = k0 + 16 + bkq * 4;
            int gn = n0 + bn;
            bR = (k < KB0) ? *(const float4*)(B0 + (size_t)gn * KB0 + k)
                           : *(const float4*)(B1 + (size_t)gn * KB1 + (k - KB0));
        }

#pragma unroll
        for (int ks = 0; ks < 2; ks++) {
            const int kk = ks * 8;
            uint32_t a[2][4];
#pragma unroll
            for (int mi = 0; mi < 2; mi++) {
                int row = wm + mi * 16 + r;
                a[mi][0] = As[row * TP + kk + c];
                a[mi][1] = As[(row + 8) * TP + kk + c];
                a[mi][2] = As[row * TP + kk + c + 4];
                a[mi][3] = As[(row + 8) * TP + kk + c + 4];
            }
            uint32_t b[4][2];
#pragma unroll
            for (int nj = 0; nj < 4; nj++) {
                int rown = wn + nj * 8 + r;
                b[nj][0] = Bs[rown * TP + kk + c];
                b[nj][1] = Bs[rown * TP + kk + c + 4];
            }
#pragma unroll
            for (int mi = 0; mi < 2; mi++)
#pragma unroll
                for (int nj = 0; nj < 4; nj++) {
                    asm volatile(
                        "mma.sync.aligned.m16n8k8.row.col.f32.tf32.tf32.f32 "
                        "{%0,%1,%2,%3}, {%4,%5,%6,%7}, {%8,%9}, {%0,%1,%2,%3};"
                        : "+f"(acc[mi][nj][0]), "+f"(acc[mi][nj][1]),
                          "+f"(acc[mi][nj][2]), "+f"(acc[mi][nj][3])
                        : "r"(a[mi][0]), "r"(a[mi][1]), "r"(a[mi][2]), "r"(a[mi][3]),
                          "r"(b[nj][0]), "r"(b[nj][1]));
                }
        }
        __syncthreads();
    }

#pragma unroll
    for (int mi = 0; mi < 2; mi++) {
        int gm = wm + mi * 16 + r;
#pragma unroll
        for (int nj = 0; nj < 4; nj++) {
            int gn = n0 + wn + nj * 8 + c * 2;
            atomicAdd(&C[(size_t)gm * N + gn],           acc[mi][nj][0]);
            atomicAdd(&C[(size_t)gm * N + gn + 1],       acc[mi][nj][1]);
            atomicAdd(&C[(size_t)(gm + 8) * N + gn],     acc[mi][nj][2]);
            atomicAdd(&C[(size_t)(gm + 8) * N + gn + 1], acc[mi][nj][3]);
        }
    }
}

// ---------------------------------------------------------------------------
// online softmax helpers
// ---------------------------------------------------------------------------
__device__ __forceinline__ void online_upd(float& m, float& s, float v) {
    if (v > m) { s = s * __expf(m - v) + 1.f; m = v; }
    else       { s += __expf(v - m); }
}
__device__ __forceinline__ void online_merge(float& m, float& s, float m2, float s2) {
    float M = fmaxf(m, m2);
    s = s * __expf(m - M) + s2 * __expf(m2 - M);
    m = M;
}

// ---------------------------------------------------------------------------
// Vocab GEMM (bf16 MMA, BK=32, register double-buffered) with fused softmax
// partials; fp16 logits out. (R13 version — best known.)
// ---------------------------------------------------------------------------
#define VPITCH 40

__global__ __launch_bounds__(256) void vocab_gemm_mma(
    const __nv_bfloat16* __restrict__ Abf,   // [128][512]
    const float* __restrict__ B,             // [VV][512]
    const float* __restrict__ bias,
    __half* __restrict__ C,                  // [128][VVP] fp16
    float* __restrict__ pmax,
    float* __restrict__ psum)
{
    __shared__ __nv_bfloat16 As[128 * VPITCH];
    __shared__ __nv_bfloat16 Bs[128 * VPITCH];

    const int tid  = threadIdx.x;
    const int n0   = blockIdx.x * 128;
    const int wid  = tid >> 5;
    const int lane = tid & 31;
    const int warp_m = (wid & 3) * 32;
    const int warp_n = (wid >> 2) * 64;

    const uint32_t as_base = (uint32_t)__cvta_generic_to_shared(As);
    const uint32_t bs_base = (uint32_t)__cvta_generic_to_shared(Bs);

    float acc[2][8][4];
#pragma unroll
    for (int i = 0; i < 2; i++)
#pragma unroll
        for (int j = 0; j < 8; j++)
#pragma unroll
            for (int t = 0; t < 4; t++) acc[i][j][t] = 0.f;

    uint4  aR[2];
    float4 bR[4];

#pragma unroll
    for (int r = 0; r < 2; r++) {
        int slot = tid + r * 256;
        int m = slot >> 2, kq = slot & 3;
        aR[r] = *(const uint4*)(Abf + (size_t)m * 512 + kq * 8);
    }
#pragma unroll
    for (int r = 0; r < 4; r++) {
        int slot = tid + r * 256;
        int n = slot >> 3, c4 = slot & 7;
        int gn = n0 + n;
        bR[r] = make_float4(0.f, 0.f, 0.f, 0.f);
        if (gn < VV) bR[r] = *(const float4*)(B + (size_t)gn * 512 + c4 * 4);
    }

    for (int k0 = 0; k0 < 512; k0 += 32) {
#pragma unroll
        for (int r = 0; r < 2; r++) {
            int slot = tid + r * 256;
            int m = slot >> 2, kq = slot & 3;
            *(uint4*)(As + m * VPITCH + kq * 8) = aR[r];
        }
#pragma unroll
        for (int r = 0; r < 4; r++) {
            int slot = tid + r * 256;
            int n = slot >> 3, c4 = slot & 7;
            __nv_bfloat162* dst = (__nv_bfloat162*)(Bs + n * VPITCH + c4 * 4);
            dst[0] = __floats2bfloat162_rn(bR[r].x, bR[r].y);
            dst[1] = __floats2bfloat162_rn(bR[r].z, bR[r].w);
        }
        __syncthreads();

        if (k0 + 32 < 512) {
#pragma unroll
            for (int r = 0; r < 2; r++) {
                int slot = tid + r * 256;
                int m = slot >> 2, kq = slot & 3;
                aR[r] = *(const uint4*)(Abf + (size_t)m * 512 + k0 + 32 + kq * 8);
            }
#pragma unroll
            for (int r = 0; r < 4; r++) {
                int slot = tid + r * 256;
                int n = slot >> 3, c4 = slot & 7;
                int gn = n0 + n;
                bR[r] = make_float4(0.f, 0.f, 0.f, 0.f);
                if (gn < VV)
                    bR[r] = *(const float4*)(B + (size_t)gn * 512 + k0 + 32 + c4 * 4);
            }
        }

#pragma unroll
        for (int kk = 0; kk < 2; kk++) {
            const int kb = kk * 16;
            uint32_t a[2][4];
#pragma unroll
            for (int mi = 0; mi < 2; mi++) {
                int row = warp_m + mi * 16 + (lane & 15);
                int col = kb + (lane >> 4) * 8;
                uint32_t addr = as_base + (row * VPITCH + col) * 2;
                asm volatile(
                    "ldmatrix.sync.aligned.m8n8.x4.shared.b16 {%0,%1,%2,%3}, [%4];"
                    : "=r"(a[mi][0]), "=r"(a[mi][1]), "=r"(a[mi][2]), "=r"(a[mi][3])
                    : "r"(addr));
            }
            uint32_t b[8][2];
#pragma unroll
            for (int nq = 0; nq < 4; nq++) {
                int g = lane >> 3;
                int within = lane & 7;
                int row_n = warp_n + nq * 16 + within + (g >> 1) * 8;
                int colk = kb + (g & 1) * 8;
                uint32_t addr = bs_base + (row_n * VPITCH + colk) * 2;
                uint32_t r0, r1, r2, r3;
                asm volatile(
                    "ldmatrix.sync.aligned.m8n8.x4.shared.b16 {%0,%1,%2,%3}, [%4];"
                    : "=r"(r0), "=r"(r1), "=r"(r2), "=r"(r3)
                    : "r"(addr));
                b[nq * 2 + 0][0] = r0; b[nq * 2 + 0][1] = r1;
                b[nq * 2 + 1][0] = r2; b[nq * 2 + 1][1] = r3;
            }
#pragma unroll
            for (int mi = 0; mi < 2; mi++)
#pragma unroll
                for (int nj = 0; nj < 8; nj++) {
                    asm volatile(
                        "mma.sync.aligned.m16n8k16.row.col.f32.bf16.bf16.f32 "
                        "{%0,%1,%2,%3}, {%4,%5,%6,%7}, {%8,%9}, {%0,%1,%2,%3};"
                        : "+f"(acc[mi][nj][0]), "+f"(acc[mi][nj][1]),
                          "+f"(acc[mi][nj][2]), "+f"(acc[mi][nj][3])
                        : "r"(a[mi][0]), "r"(a[mi][1]), "r"(a[mi][2]), "r"(a[mi][3]),
                          "r"(b[nj][0]), "r"(b[nj][1]));
                }
        }
        __syncthreads();
    }

    // epilogue: bias + half2 store + per-row online stats
    const int pblock = blockIdx.x * 2 + (warp_n ? 1 : 0);
#pragma unroll
    for (int mi = 0; mi < 2; mi++) {
        int m = warp_m + mi * 16 + (lane >> 2);
        float m0v = -3.0e38f, s0 = 0.f;
        float m1v = -3.0e38f, s1 = 0.f;
#pragma unroll
        for (int nj = 0; nj < 8; nj++) {
            int n = n0 + warp_n + nj * 8 + (lane & 3) * 2;   // even
            if (n + 1 < VV) {
                float v0 = acc[mi][nj][0] + bias[n];
                float v1 = acc[mi][nj][1] + bias[n + 1];
                *(__half2*)(C + (size_t)m * VVP + n) = __floats2half2_rn(v0, v1);
                online_upd(m0v, s0, v0); online_upd(m0v, s0, v1);
                float w0 = acc[mi][nj][2] + bias[n];
                float w1 = acc[mi][nj][3] + bias[n + 1];
                *(__half2*)(C + (size_t)(m + 8) * VVP + n) = __floats2half2_rn(w0, w1);
                online_upd(m1v, s1, w0); online_upd(m1v, s1, w1);
            } else if (n < VV) {
                float v0 = acc[mi][nj][0] + bias[n];
                C[(size_t)m * VVP + n] = __float2half_rn(v0);
                online_upd(m0v, s0, v0);
                float w0 = acc[mi][nj][2] + bias[n];
                C[(size_t)(m + 8) * VVP + n] = __float2half_rn(w0);
                online_upd(m1v, s1, w0);
            }
        }
#pragma unroll
        for (int off = 1; off <= 2; off <<= 1) {
            float om = __shfl_xor_sync(0xffffffffu, m0v, off);
            float os = __shfl_xor_sync(0xffffffffu, s0, off);
            online_merge(m0v, s0, om, os);
            om = __shfl_xor_sync(0xffffffffu, m1v, off);
            os = __shfl_xor_sync(0xffffffffu, s1, off);
            online_merge(m1v, s1, om, os);
        }
        if ((lane & 3) == 0) {
            pmax[(size_t)pblock * BB + m]     = m0v;
            psum[(size_t)pblock * BB + m]     = s0;
            pmax[(size_t)pblock * BB + m + 8] = m1v;
            psum[(size_t)pblock * BB + m + 8] = s1;
        }
    }
}

// ---------------------------------------------------------------------------
// Fused: per-row stats reduce + final vocab distribution + copy scatter.
// ---------------------------------------------------------------------------
#define FCHUNK 6290   // even; 8*6290 >= VEXTN

__global__ __launch_bounds__(256) void final_fused_kernel(
    const __half* __restrict__ logits,
    const float* __restrict__ pmax,
    const float* __restrict__ psum,
    const float* __restrict__ pgen,
    const int*   __restrict__ ids,    // [BB][SS]
    const float* __restrict__ attn,   // [BB][SS]
    float* __restrict__ outf)
{
    const int b = blockIdx.y;
    const int tid = threadIdx.x;

    float m = -3.0e38f, s = 0.f;
    for (int i = tid; i < NPART; i += 256)
        online_merge(m, s, pmax[(size_t)i * BB + b], psum[(size_t)i * BB + b]);
    __shared__ float sm[256], ss[256];
    sm[tid] = m; ss[tid] = s; __syncthreads();
    for (int off = 128; off; off >>= 1) {
        if (tid < off) {
            float M = fmaxf(sm[tid], sm[tid + off]);
            ss[tid] = ss[tid] * __expf(sm[tid] - M) + ss[tid + off] * __expf(sm[tid + off] - M);
            sm[tid] = M;
        }
        __syncthreads();
    }
    m = sm[0]; s = ss[0];
    const float pg = pgen[b];
    const float scale = pg / s;

    const int start = blockIdx.x * FCHUNK;
    const int end = (start + FCHUNK < VEXTN) ? (start + FCHUNK) : VEXTN;
    const __half* lrow = logits + (size_t)b * VVP;
    float* orow = outf + (size_t)b * VEXTN;

    for (int n = start + tid * 2; n < end; n += 512) {
        float v0 = 0.f, v1 = 0.f;
        if (n + 1 < VV) {
            __half2 h = *(const __half2*)(lrow + n);
            float2 f = __half22float2(h);
            v0 = scale * __expf(f.x - m);
            v1 = scale * __expf(f.y - m);
        } else if (n < VV) {
            v0 = scale * __expf(__half2float(lrow[n]) - m);
        }
        orow[n] = v0;
        if (n + 1 < end) orow[n + 1] = v1;
    }

    __syncthreads();   // chunk stores complete (block-scope ordering)
    const float one_m_pg = 1.f - pg;
    for (int sidx = tid; sidx < SS; sidx += 256) {
        int id = ids[b * SS + sidx];
        if (id >= start && id < end) {
            atomicAdd(&orow[id], one_m_pg * attn[b * SS + sidx]);
        }
    }
}

// ---------------------------------------------------------------------------
// LSTM elementwise (float4 vectorized)
// ---------------------------------------------------------------------------
__global__ void lstm_elem(const float* __restrict__ gates,
                          const float* __restrict__ b_hh,
                          const float* __restrict__ c0,
                          float* __restrict__ h1, float* __restrict__ c1,
                          float* __restrict__ out_h1, float* __restrict__ out_c1)
{
    int idx = blockIdx.x * blockDim.x + threadIdx.x;
    if (idx >= BB * HH / 4) return;
    int b  = idx / (HH / 4);
    int j  = (idx % (HH / 4)) * 4;
    const float* g = gates + (size_t)b * 4 * HH;
    float4 gi = *(const float4*)(g + j);
    float4 gf = *(const float4*)(g + HH + j);
    float4 gg = *(const float4*)(g + 2 * HH + j);
    float4 go = *(const float4*)(g + 3 * HH + j);
    float4 bi = *(const float4*)(b_hh + j);
    float4 bf = *(const float4*)(b_hh + HH + j);
    float4 bg = *(const float4*)(b_hh + 2 * HH + j);
    float4 bo = *(const float4*)(b_hh + 3 * HH + j);
    float4 cprev = *(const float4*)(c0 + b * HH + j);

    float4 cc, hh;
    {
        float iv = sigmoidf_(gi.x + bi.x), fv = sigmoidf_(gf.x + bf.x);
        float gv = tanhf(gg.x + bg.x),     ov = sigmoidf_(go.x + bo.x);
        cc.x = fv * cprev.x + iv * gv; hh.x = ov * tanhf(cc.x);
        iv = sigmoidf_(gi.y + bi.y); fv = sigmoidf_(gf.y + bf.y);
        gv = tanhf(gg.y + bg.y);     ov = sigmoidf_(go.y + bo.y);
        cc.y = fv * cprev.y + iv * gv; hh.y = ov * tanhf(cc.y);
        iv = sigmoidf_(gi.z + bi.z); fv = sigmoidf_(gf.z + bf.z);
        gv = tanhf(gg.z + bg.z);     ov = sigmoidf_(go.z + bo.z);
        cc.z = fv * cprev.z + iv * gv; hh.z = ov * tanhf(cc.z);
        iv = sigmoidf_(gi.w + bi.w); fv = sigmoidf_(gf.w + bf.w);
        gv = tanhf(gg.w + bg.w);     ov = sigmoidf_(go.w + bo.w);
        cc.w = fv * cprev.w + iv * gv; hh.w = ov * tanhf(cc.w);
    }
    *(float4*)(h1 + b * HH + j) = hh;
    *(float4*)(c1 + b * HH + j) = cc;
    *(float4*)(out_h1 + b * HH + j) = hh;
    *(float4*)(out_c1 + b * HH + j) = cc;
}

// ---------------------------------------------------------------------------
// Attention energies (warp per (b,s) row), tanh.approx
// ---------------------------------------------------------------------------
__global__ void attn_e_kernel(const float* __restrict__ sf,
                              const float* __restrict__ dec_fea,
                              const float* __restrict__ cov,
                              const float* __restrict__ mask,
                              const float* __restrict__ v_att,
                              const float* __restrict__ w_c,
                              float* __restrict__ e)
{
    int gwarp = (blockIdx.x * blockDim.x + threadIdx.x) >> 5;
    int lane = threadIdx.x & 31;
    if (gwarp >= BB * SS) return;
    int b = gwarp / SS;
    float cadd = w_c[0] * cov[gwarp];

    const float4* row = (const float4*)(sf + (size_t)gwarp * HH);
    const float4* df  = (const float4*)(dec_fea + (size_t)b * HH);
    const float4* va  = (const float4*)(v_att);

    float acc = 0.f;
#pragma unroll
    for (int i = 0; i < HH / 128; i++) {
        float4 x = row[i * 32 + lane];
        float4 d = df[i * 32 + lane];
        float4 v = va[i * 32 + lane];
        acc += tanh_approx(x.x + d.x + cadd) * v.x;
        acc += tanh_approx(x.y + d.y + cadd) * v.y;
        acc += tanh_approx(x.z + d.z + cadd) * v.z;
        acc += tanh_approx(x.w + d.w + cadd) * v.w;
    }
#pragma unroll
    for (int off = 16; off; off >>= 1) acc += __shfl_xor_sync(0xffffffffu, acc, off);
    if (lane == 0) e[gwarp] = (mask[gwarp] > 0.f) ? acc : -1.0e9f;
}

// ---------------------------------------------------------------------------
// Fused softmax + context: grid (B, 1, CSPLIT), 128 threads.
// Each block recomputes the row softmax stats (cheap: 400 values) and then
// handles its own s-chunk: attn/coverage writes (disjoint chunks) + partial
// context accumulation (atomicAdd into pre-zeroed ctx).
// ---------------------------------------------------------------------------
#define CSPLIT 4
#define CCHUNK (SS / CSPLIT)   // 100

__global__ __launch_bounds__(128) void ctx_fused_kernel(
    const float* __restrict__ e,
    const float* __restrict__ mask,
    const float* __restrict__ cov,
    const float* __restrict__ states,
    float* __restrict__ out_attn,
    float* __restrict__ out_cov,
    float* __restrict__ ctx)
{
    const int b = blockIdx.x;
    const int s0 = blockIdx.z * CCHUNK;
    const int tid = threadIdx.x;

    __shared__ float se[SS];
    __shared__ float sa[CCHUNK];
    __shared__ float r1[128], r2[128];

    // load full e row
    for (int s = tid; s < SS; s += 128) se[s] = e[b * SS + s];
    __syncthreads();

    // row max
    float m = -3.0e38f;
    for (int s = tid; s < SS; s += 128) m = fmaxf(m, se[s]);
    r1[tid] = m; __syncthreads();
    for (int off = 64; off; off >>= 1) {
        if (tid < off) r1[tid] = fmaxf(r1[tid], r1[tid + off]);
        __syncthreads();
    }
    m = r1[0];
    __syncthreads();

    // P = sum exp, Q = sum exp*mask
    float P = 0.f, Q = 0.f;
    for (int s = tid; s < SS; s += 128) {
        float p = __expf(se[s] - m);
        P += p;
        Q += p * mask[b * SS + s];
    }
    r1[tid] = P; r2[tid] = Q; __syncthreads();
    for (int off = 64; off; off >>= 1) {
        if (tid < off) { r1[tid] += r1[tid + off]; r2[tid] += r2[tid + off]; }
        __syncthreads();
    }
    P = r1[0]; Q = r2[0];
    const float denom = Q / P + 1e-12f;

    // attn for own chunk (+ disjoint-chunk output writes)
    if (tid < CCHUNK) {
        int s = s0 + tid;
        float a = __expf(se[s] - m) * mask[b * SS + s] / P / denom;
        sa[tid] = a;
        out_attn[b * SS + s] = a;
        out_cov[b * SS + s] = cov[b * SS + s] + a;
    }
    __syncthreads();

    // context partial over own chunk (float4 over h)
    const float4* st = (const float4*)(states + (size_t)b * SS * HH + (size_t)s0 * HH)
                       + tid;
    float4 a0 = make_float4(0.f, 0.f, 0.f, 0.f);
    float4 a1 = make_float4(0.f, 0.f, 0.f, 0.f);
    float4 a2 = make_float4(0.f, 0.f, 0.f, 0.f);
    float4 a3 = make_float4(0.f, 0.f, 0.f, 0.f);
#pragma unroll 5
    for (int s = 0; s < CCHUNK; s += 4) {
        float4 v0 = st[(size_t)(s)     * (HH / 4)];
        float4 v1 = st[(size_t)(s + 1) * (HH / 4)];
        float4 v2 = st[(size_t)(s + 2) * (HH / 4)];
        float4 v3 = st[(size_t)(s + 3) * (HH / 4)];
        float c0 = sa[s], c1 = sa[s + 1], c2 = sa[s + 2], c3 = sa[s + 3];
        a0.x += c0 * v0.x; a0.y += c0 * v0.y; a0.z += c0 * v0.z; a0.w += c0 * v0.w;
        a1.x += c1 * v1.x; a1.y += c1 * v1.y; a1.z += c1 * v1.z; a1.w += c1 * v1.w;
        a2.x += c2 * v2.x; a2.y += c2 * v2.y; a2.z += c2 * v2.z; a2.w += c2 * v2.w;
        a3.x += c3 * v3.x; a3.y += c3 * v3.y; a3.z += c3 * v3.z; a3.w += c3 * v3.w;
    }
    float rx = (a0.x + a1.x) + (a2.x + a3.x);
    float ry = (a0.y + a1.y) + (a2.y + a3.y);
    float rz = (a0.z + a1.z) + (a2.z + a3.z);
    float rw = (a0.w + a1.w) + (a2.w + a3.w);
    float* dst = ctx + b * HH + tid * 4;
    atomicAdd(dst + 0, rx);
    atomicAdd(dst + 1, ry);
    atomicAdd(dst + 2, rz);
    atomicAdd(dst + 3, rw);
}

// ---------------------------------------------------------------------------
// p_gen = sigmoid(dec_out . W_pg + b_pg); copy dec_out to output; bf16 convert
// ---------------------------------------------------------------------------
__global__ void pgen_kernel(const float* __restrict__ dec_out,
                            const float* __restrict__ W_pg,
                            const float* __restrict__ b_pg,
                            float* __restrict__ pgen,
                            float* __restrict__ out_pgen,
                            float* __restrict__ out_dec,
                            __nv_bfloat16* __restrict__ dec_bf)
{
    int b = blockIdx.x;
    int tid = threadIdx.x;            // 128 threads
    float acc = 0.f;
    for (int j = tid; j < HH; j += 128) {
        float d = dec_out[b * HH + j];
        out_dec[b * HH + j] = d;
        dec_bf[b * HH + j] = __float2bfloat16_rn(d);
        acc += d * W_pg[j];
    }
    __shared__ float red[4];
#pragma unroll
    for (int off = 16; off; off >>= 1) acc += __shfl_xor_sync(0xffffffffu, acc, off);
    if ((tid & 31) == 0) red[tid >> 5] = acc;
    __syncthreads();
    if (tid == 0) {
        float t = red[0] + red[1] + red[2] + red[3];
        float p = sigmoidf_(t + b_pg[0]);
        pgen[b] = p;
        out_pgen[b] = p;
    }
}

// ---------------------------------------------------------------------------
// Launcher
// ---------------------------------------------------------------------------
extern "C" void kernel_launch(void* const* d_in, const int* in_sizes, int n_in,
                              void* d_out, int out_size)
{
    const float* emb    = (const float*)d_in[0];
    const float* feed   = (const float*)d_in[1];
    const float* hidden = (const float*)d_in[2];
    const float* ctx0   = (const float*)d_in[3];
    const float* states = (const float*)d_in[4];
    const float* sfeat  = (const float*)d_in[5];
    const float* mask   = (const float*)d_in[6];
    const float* cov    = (const float*)d_in[7];
    const int*   srcids = (const int*)d_in[8];
    const float* W_ic   = (const float*)d_in[9];
    const float* b_ic   = (const float*)d_in[10];
    const float* W_ih   = (const float*)d_in[11];
    const float* W_hh   = (const float*)d_in[12];
    const float* b_ih   = (const float*)d_in[13];
    const float* b_hh   = (const float*)d_in[14];
    const float* W_dec  = (const float*)d_in[15];
    const float* b_att  = (const float*)d_in[16];
    const float* v_att  = (const float*)d_in[17];
    const float* w_c    = (const float*)d_in[18];
    const float* W_out  = (const float*)d_in[19];
    const float* b_out  = (const float*)d_in[20];
    const float* W_pg   = (const float*)d_in[21];
    const float* b_pg   = (const float*)d_in[22];
    const float* W_v    = (const float*)d_in[23];
    const float* b_v    = (const float*)d_in[24];

    float* out = (float*)d_out;
    float* out_final = out;
    float* out_pgen  = out_final + (size_t)BB * VEXTN;
    float* out_attn  = out_pgen + BB;
    float* out_cov   = out_attn + (size_t)BB * SS;
    float* out_h1    = out_cov + (size_t)BB * SS;
    float* out_c1    = out_h1 + (size_t)BB * HH;
    float* out_dec   = out_c1 + (size_t)BB * HH;

    float *px, *pgates, *ph1, *pc1, *pdecfea, *pctx, *pdecout;
    float *pe, *ppgen, *ppmax, *ppsum;
    __half* plogits;
    __nv_bfloat16* pdecbf;
    cudaGetSymbolAddress((void**)&px,      g_x);
    cudaGetSymbolAddress((void**)&pgates,  g_gates);
    cudaGetSymbolAddress((void**)&ph1,     g_h1);
    cudaGetSymbolAddress((void**)&pc1,     g_c1);
    cudaGetSymbolAddress((void**)&pdecfea, g_decfea);
    cudaGetSymbolAddress((void**)&pctx,    g_ctx);
    cudaGetSymbolAddress((void**)&pdecout, g_decout);
    cudaGetSymbolAddress((void**)&pdecbf,  g_dec_bf);
    cudaGetSymbolAddress((void**)&pe,      g_e);
    cudaGetSymbolAddress((void**)&ppgen,   g_pgen);
    cudaGetSymbolAddress((void**)&ppmax,   g_pmax);
    cudaGetSymbolAddress((void**)&ppsum,   g_psum);
    cudaGetSymbolAddress((void**)&plogits, g_logits);

    // 0) fused init (bias fills + ctx zero)
    fill_bias_all<<<524288 / 256, 256>>>(px, b_ic, pgates, b_ih,
                                         pdecfea, b_att, pdecout, b_out, pctx);

    // 1) x = [emb|feed] @ W_ic^T   (tf32, split 8)
    gemm_tf32_splitk<<<dim3(EE / 64, 1, 8), 256>>>(
        EE, 1024, 128, emb, EE, feed, W_ic, 1024, nullptr, px);

    // 2) gates = [x|h0] @ [W_ih|W_hh]^T   (tf32, split 8)
    gemm_tf32_splitk<<<dim3(4 * HH / 64, 1, 8), 256>>>(
        4 * HH, 1024, 128, px, EE, hidden, W_ih, EE, W_hh, pgates);

    // 3) LSTM elementwise
    lstm_elem<<<(BB * HH / 4 + 255) / 256, 256>>>(pgates, b_hh, ctx0, ph1, pc1,
                                                  out_h1, out_c1);

    // 4) dec_fea = h1 @ W_dec^T   (tf32, split 8)
    gemm_tf32_splitk<<<dim3(HH / 64, 1, 8), 256>>>(
        HH, 512, 64, ph1, 512, nullptr, W_dec, 512, nullptr, pdecfea);

    // 5) attention energies
    attn_e_kernel<<<(BB * SS) / 8, 256>>>(sfeat, pdecfea, cov, mask, v_att, w_c, pe);

    // 6) fused softmax + coverage + context (512 blocks)
    ctx_fused_kernel<<<dim3(BB, 1, CSPLIT), 128>>>(pe, mask, cov, states,
                                                   out_attn, out_cov, pctx);

    // 7) dec_out = [h1|ctx] @ W_out^T   (tf32, split 8)
    gemm_tf32_splitk<<<dim3(HH / 64, 1, 8), 256>>>(
        HH, 1024, 128, ph1, HH, pctx, W_out, 1024, nullptr, pdecout);

    // 8) p_gen + dec_out output copy + bf16 convert
    pgen_kernel<<<BB, 128>>>(pdecout, W_pg, b_pg, ppgen, out_pgen, out_dec, pdecbf);

    // 9) vocab logits (bf16 MMA, BK=32) + fused softmax partials
    vocab_gemm_mma<<<NPB, 256>>>(pdecbf, W_v, b_v, plogits, ppmax, ppsum);

    // 10) fused stats reduce + final vocab distribution + copy scatter
    final_fused_kernel<<<dim3(8, BB), 256>>>(plogits, ppmax, ppsum, ppgen,
                                             srcids, out_attn, out_final);
}